// round 6
// baseline (speedup 1.0000x reference)
#include <cuda_runtime.h>
#include <cstdint>

typedef unsigned long long ull;

#define BB   512
#define TT   2000
#define HH   128
#define NI   13
#define GG   512          // 4*H gate columns
#define BC   4            // batch per CTA
#define NBLK (BB/BC)      // 128 CTAs
#define NTHR 256
#define WS_K 104          // weight k-rows cached in smem (208 KB)

// -------- device scratch (static: allocation-free rule) --------
__device__ __align__(16) float d_Wstream[72*GG];     // layer1 streamed rows, transposed [72][512]
__device__ float d_h1[(size_t)BB*TT*HH];             // layer0 hidden sequence (524 MB)

// -------- packed f32x2 helpers --------
__device__ __forceinline__ ull pack2(float x, float y){
    ull r; asm("mov.b64 %0,{%1,%2};" : "=l"(r) : "f"(x), "f"(y)); return r;
}
__device__ __forceinline__ ull dup2(float x){ return pack2(x, x); }
__device__ __forceinline__ ull ffma2(ull a, ull b, ull c){
    ull d; asm("fma.rn.f32x2 %0,%1,%2,%3;" : "=l"(d) : "l"(a), "l"(b), "l"(c)); return d;
}

// accurate (expf-based) activations for the c-accumulation path
__device__ __forceinline__ float sigf(float x){
    return __fdividef(1.0f, 1.0f + __expf(-x));
}
__device__ __forceinline__ float tanh_(float x){
    return 1.0f - __fdividef(2.0f, __expf(2.0f*x) + 1.0f);
}
// HW tanh (MUFU.TANH) for the output path (no long-horizon accumulation)
__device__ __forceinline__ float tanhap(float x){
    float y; asm("tanh.approx.f32 %0,%1;" : "=f"(y) : "f"(x)); return y;
}

// -------- persistent LSTM layer kernel --------
// Thread tid owns gate cols (2*tid, 2*tid+1) for 4 batches in the GEMV,
// and (h-index tid&127, batches 2*(tid>>7)+{0,1}) in the state update.
// Weight residency: rows [0,WS) smem, [WS,WS+RR) registers; layer1 streams the
// remaining 72 rows from L2 (pre-transposed in d_Wstream) with 2-chunk lookahead.
template<int LAYER>
__global__ void __launch_bounds__(NTHR, 1) lstm_layer(
        const float* __restrict__ xin_param,
        const float* __restrict__ Wih,  const float* __restrict__ Whh,
        const float* __restrict__ bih,  const float* __restrict__ bhh,
        const float* __restrict__ Whh1, // layer0 only: source for d_Wstream fill
        const float* __restrict__ Wfc,  const float* __restrict__ bfc,
        float* __restrict__ out)
{
    constexpr int IN = (LAYER == 0) ? NI : HH;
    constexpr int K  = IN + HH;
    constexpr int WS = WS_K;                             // 104 smem rows
    constexpr int RR = (LAYER == 0) ? (K - WS) : 80;     // register rows
    constexpr int S0 = WS + RR;                          // first streamed row
    constexpr int NS = K - S0;                           // streamed rows (0 or 72)
    constexpr int CH = 4;                                // stream chunk rows
    constexpr int NCH = (NS > 0) ? NS/CH : 0;            // 18 for layer1

    extern __shared__ ull smem_u[];
    ull* ws2 = smem_u;                 // [WS][256] weight ull per thread-colpair
    ull* hd2 = ws2 + WS*256;           // [K][4] dup-packed inputs/h per batch
    ull* gs2 = hd2 + (size_t)K*4;      // [4][256] gate pre-activations
    float* gsf = (float*)gs2;          // float view [b][512]

    const float* xin = (LAYER == 0) ? xin_param : d_h1;

    const int tid = threadIdx.x;
    const int b0  = blockIdx.x * BC;

    // combined-weight element (k, j): k<IN -> Wih[j][k], else Whh[j][k-IN]
    auto gw = [&](int k, int j) -> float {
        return (k < IN) ? __ldg(&Wih[j*IN + k]) : __ldg(&Whh[j*HH + (k - IN)]);
    };

    // layer0 also publishes layer1's streamed rows (transposed, coalesced writes).
    // lstm1 launches after lstm0 completes, so ordering is by kernel boundary.
    if (LAYER == 0) {
        int gt = blockIdx.x * NTHR + tid;
        for (int i = gt; i < 72*GG; i += NBLK*NTHR) {
            int r = i >> 9, j = i & (GG-1);
            d_Wstream[i] = __ldg(&Whh1[j*HH + (56 + r)]);
        }
    }

    // tier 1: smem weight cache (gathered once; L2-hot since all CTAs read same)
    for (int idx = tid; idx < WS*256; idx += NTHR) {
        int k = idx >> 8, cp = idx & 255;
        ws2[idx] = pack2(gw(k, 2*cp), gw(k, 2*cp + 1));
    }
    // tier 2: register weight cache
    ull wreg[RR];
    #pragma unroll
    for (int r = 0; r < RR; ++r) wreg[r] = pack2(gw(WS + r, 2*tid), gw(WS + r, 2*tid + 1));

    // zero recurrent-h region of hd
    for (int i = tid; i < HH*4; i += NTHR) hd2[IN*4 + i] = 0ull;

    const ull bi = pack2(__ldg(&bih[2*tid])   + __ldg(&bhh[2*tid]),
                         __ldg(&bih[2*tid+1]) + __ldg(&bhh[2*tid+1]));

    float cst[2] = {0.f, 0.f};
    const int dj  = tid & (HH-1);        // h index for phase D
    const int db  = (tid >> 7) * 2;      // first of 2 batches for phase D

    // ---- xin prefetch state ----
    const int pfb = (LAYER == 0) ? ((tid < BC*NI) ? tid/NI : 0) : (tid >> 6);
    const int pfk = (LAYER == 0) ? ((tid < BC*NI) ? tid - pfb*NI : 0) : 2*(tid & 63);
    const float* xpf = xin + ((size_t)(b0 + pfb)*TT + 0)*IN + pfk;
    float pf0 = 0.f, pf1 = 0.f;
    if (LAYER == 0) { if (tid < BC*NI) pf0 = __ldg(xpf); }
    else            { float2 v = __ldg((const float2*)xpf); pf0 = v.x; pf1 = v.y; }

    __syncthreads();

    const ulonglong2* hdq = (const ulonglong2*)hd2;

    for (int t = 0; t < TT; ++t) {
        // ---- phase A: publish this step's input slice (dup-packed) ----
        if (LAYER == 0) {
            if (tid < BC*NI) hd2[pfk*4 + pfb] = dup2(pf0);
        } else {
            hd2[pfk*4 + pfb]     = dup2(pf0);
            hd2[(pfk+1)*4 + pfb] = dup2(pf1);
        }
        __syncthreads();   // covers phase-A writes AND prev-step recurrent-h writes

        // prefetch next step's input (latency hidden behind phase B)
        if (t + 1 < TT) {
            const float* p = xpf + (size_t)(t+1)*IN;
            if (LAYER == 0) { if (tid < BC*NI) pf0 = __ldg(p); }
            else            { float2 v = __ldg((const float2*)p); pf0 = v.x; pf1 = v.y; }
        }

        // ---- phase B: gate pre-activations ----
        ull a0 = bi, a1 = bi, a2 = bi, a3 = bi;

        auto rowfma = [&](ull w, int row){
            ulonglong2 hA = hdq[row*2];
            ulonglong2 hB = hdq[row*2 + 1];
            a0 = ffma2(hA.x, w, a0);  a1 = ffma2(hA.y, w, a1);
            a2 = ffma2(hB.x, w, a2);  a3 = ffma2(hB.y, w, a3);
        };

        if (NS > 0) {
            const ull* sbase = (const ull*)d_Wstream + tid;
            ull buf[3][CH];
            auto ldch = [&](ull* b, int c){
                const ull* p = sbase + (size_t)c*CH*256;
                #pragma unroll
                for (int i = 0; i < CH; ++i) b[i] = __ldg(p + i*256);
            };

            ldch(buf[0], 0);            // 2-chunk lookahead from the start,
            ldch(buf[1], 1);            // covered by the register tier below
            #pragma unroll
            for (int r = 0; r < RR; ++r) rowfma(wreg[r], WS + r);

            // 18 chunk iterations, fully unrolled; smem segments: 14x6 + 4x5 = 104
            #pragma unroll
            for (int c = 0; c < NCH; ++c) {
                if (c + 2 < NCH) ldch(buf[(c+2)%3], c+2);
                #pragma unroll
                for (int i = 0; i < CH; ++i) rowfma(buf[c%3][i], S0 + c*CH + i);
                const int k0 = (c < 14) ? 6*c : 84 + 5*(c-14);
                const int n  = (c < 14) ? 6 : 5;
                #pragma unroll
                for (int k = 0; k < n; ++k) rowfma(ws2[(k0+k)*256 + tid], k0 + k);
            }
        } else {
            #pragma unroll
            for (int r = 0; r < RR; ++r) rowfma(wreg[r], WS + r);
            #pragma unroll 8
            for (int k = 0; k < WS; ++k) rowfma(ws2[k*256 + tid], k);
        }

        // ---- phase C: publish gate pre-activations ----
        gs2[0*256 + tid] = a0;
        gs2[1*256 + tid] = a1;
        gs2[2*256 + tid] = a2;
        gs2[3*256 + tid] = a3;
        __syncthreads();

        // ---- phase D: gates + state update (thread -> (dj, 2 batches)) ----
        #pragma unroll
        for (int q = 0; q < 2; ++q) {
            int b = db + q;
            float gi = gsf[b*GG +          dj];
            float gf = gsf[b*GG +   HH  +  dj];
            float gg = gsf[b*GG + 2*HH  +  dj];
            float go = gsf[b*GG + 3*HH  +  dj];
            float ig = sigf(gi);                           // accurate: feeds c integral
            float fg = sigf(gf);                           // accurate
            float gv = tanh_(gg);                          // accurate
            float og = fmaf(tanhap(0.5f*go), 0.5f, 0.5f);  // approx: output path
            float c  = fg*cst[q] + ig*gv;
            cst[q] = c;
            float h = og * tanhap(c);                      // approx: output path
            hd2[(IN + dj)*4 + b] = dup2(h);
            if (LAYER == 0) {
                d_h1[((size_t)(b0 + b)*TT + t)*HH + dj] = h;
            }
        }
        // next iteration's phase-A sync orders D's hd2 writes before the k-loop
    }

    // ---- fused FC epilogue (layer 1 only): out[b][c] = h . Wfc[c] + bfc[c] ----
    if (LAYER == 1) {
        __syncthreads();                   // all final h visible in hd2
        int g = tid >> 4;                  // 16 groups of 16 threads
        int l = tid & 15;
        int b = g >> 2, c = g & 3;
        float s = 0.f;
        #pragma unroll
        for (int q = 0; q < 8; ++q) {
            int j = l + 16*q;
            float hv = ((const float*)(hd2 + (size_t)(IN + j)*4 + b))[0];
            s += hv * __ldg(&Wfc[c*HH + j]);
        }
        #pragma unroll
        for (int o = 8; o; o >>= 1) s += __shfl_xor_sync(0xffffffffu, s, o, 16);
        if (l == 0) out[(b0 + b)*4 + c] = s + __ldg(&bfc[c]);
    }
}

// -------- launch --------
extern "C" void kernel_launch(void* const* d_in, const int* in_sizes, int n_in,
                              void* d_out, int out_size)
{
    const float* x    = (const float*)d_in[0];
    const float* Wih0 = (const float*)d_in[1];
    const float* Whh0 = (const float*)d_in[2];
    const float* bih0 = (const float*)d_in[3];
    const float* bhh0 = (const float*)d_in[4];
    const float* Wih1 = (const float*)d_in[5];
    const float* Whh1 = (const float*)d_in[6];
    const float* bih1 = (const float*)d_in[7];
    const float* bhh1 = (const float*)d_in[8];
    const float* Wfc  = (const float*)d_in[9];
    const float* bfc  = (const float*)d_in[10];
    float* out = (float*)d_out;

    constexpr int K0 = NI + HH, K1 = HH + HH;
    constexpr int SMEM0 = (WS_K*256 + K0*4 + 4*256) * 8;   // 225,696 B
    constexpr int SMEM1 = (WS_K*256 + K1*4 + 4*256) * 8;   // 229,376 B

    cudaFuncSetAttribute(lstm_layer<0>, cudaFuncAttributeMaxDynamicSharedMemorySize, SMEM0);
    cudaFuncSetAttribute(lstm_layer<1>, cudaFuncAttributeMaxDynamicSharedMemorySize, SMEM1);

    lstm_layer<0><<<NBLK, NTHR, SMEM0>>>(x, Wih0, Whh0, bih0, bhh0, Whh1,
                                         nullptr, nullptr, nullptr);
    lstm_layer<1><<<NBLK, NTHR, SMEM1>>>(nullptr, Wih1, Whh1, bih1, bhh1, nullptr,
                                         Wfc, bfc, out);
}

// round 16
// speedup vs baseline: 1.4279x; 1.4279x over previous
#include <cuda_runtime.h>
#include <cstdint>

typedef unsigned long long ull;

#define BB   512
#define TT   2000
#define HH   128
#define NI   13
#define GG   512          // 4*H gate columns
#define BC   4            // batch per CTA
#define NBLK (BB/BC)      // 128 CTAs
#define NTHR 256
#define PS   52           // weight k-PAIRS cached in smem (52 pairs = 104 rows, 208 KB)
#define PSTR1 40          // layer1 streamed pairs
#define PR1  36           // layer1 register pairs  (52+36+40 = 128 pairs = 256 rows)

// -------- device scratch (static: allocation-free rule) --------
__device__ __align__(16) ulonglong2 d_Wstream2[PSTR1*256];  // layer1 streamed pairs
__device__ float d_h1[(size_t)BB*TT*HH];                    // layer0 hidden sequence

// -------- packed f32x2 helpers --------
__device__ __forceinline__ ull pack2(float x, float y){
    ull r; asm("mov.b64 %0,{%1,%2};" : "=l"(r) : "f"(x), "f"(y)); return r;
}
__device__ __forceinline__ float sum2(ull v){
    float lo, hi; asm("mov.b64 {%0,%1},%2;" : "=f"(lo), "=f"(hi) : "l"(v));
    return lo + hi;
}
__device__ __forceinline__ ull ffma2(ull a, ull b, ull c){
    ull d; asm("fma.rn.f32x2 %0,%1,%2,%3;" : "=l"(d) : "l"(a), "l"(b), "l"(c)); return d;
}

// accurate (expf-based) activations for the c-accumulation path
__device__ __forceinline__ float sigf(float x){
    return __fdividef(1.0f, 1.0f + __expf(-x));
}
__device__ __forceinline__ float tanh_(float x){
    return 1.0f - __fdividef(2.0f, __expf(2.0f*x) + 1.0f);
}
// HW tanh (MUFU.TANH) for the output path (no long-horizon accumulation)
__device__ __forceinline__ float tanhap(float x){
    float y; asm("tanh.approx.f32 %0,%1;" : "=f"(y) : "f"(x)); return y;
}

// -------- persistent LSTM layer kernel (k-paired f32x2 GEMV) --------
// Thread tid owns gate cols (2*tid, 2*tid+1) for 4 batches; f32x2 lanes pair
// ADJACENT K-ROWS (even k, odd k), so neither weights nor h need duplication.
// acc = (sum_even, sum_odd); bias folded into lane 0 at init; horizontal add at end.
// Weight pairs: [0,PS) smem, [PS,PS+PR) registers, rest streamed from L2.
template<int LAYER>
__global__ void __launch_bounds__(NTHR, 1) lstm_layer(
        const float* __restrict__ xin_param,
        const float* __restrict__ Wih,  const float* __restrict__ Whh,
        const float* __restrict__ bih,  const float* __restrict__ bhh,
        const float* __restrict__ Whh1, // layer0 only: source for d_Wstream2 fill
        const float* __restrict__ Wfc,  const float* __restrict__ bfc,
        float* __restrict__ out)
{
    constexpr int IN   = (LAYER == 0) ? NI : HH;
    constexpr int K    = IN + HH;                 // 141 / 256
    constexpr int P    = (LAYER == 0) ? 72 : 128; // k-pairs (L0 padded: rows 141..143 zero)
    constexpr int PR   = (LAYER == 0) ? (P - PS) : PR1;   // 20 / 36
    constexpr int PSTR = P - PS - PR;             // 0 / 40
    constexpr int CH   = 2;                       // stream chunk = 2 pairs
    constexpr int NCH  = (PSTR > 0) ? PSTR/CH : 0;// 0 / 20

    extern __shared__ ull smem_u[];
    ulonglong2* wsp = (ulonglong2*)smem_u;        // [PS*256] paired weights
    ull* hp  = smem_u + (size_t)PS*512;           // [P][4] h-pairs per batch
    ull* gs2 = hp + (size_t)P*4;                  // [4][256] gate pre-activations
    float* hpf = (float*)hp;
    float* gsf = (float*)gs2;

    const float* xin = (LAYER == 0) ? xin_param : d_h1;
    const int tid = threadIdx.x;
    const int b0  = blockIdx.x * BC;

    // combined-weight element (k, j); zero for padded rows k>=K
    auto gw = [&](int k, int j) -> float {
        if (k >= K) return 0.f;
        return (k < IN) ? __ldg(&Wih[j*IN + k]) : __ldg(&Whh[j*HH + (k - IN)]);
    };

    // layer0 grid also fills layer1's streamed pairs (global pairs 88..127,
    // rows 176..255 -> Whh1 cols 48..127). Ordered by kernel boundary.
    if (LAYER == 0) {
        int gt = blockIdx.x * NTHR + tid;
        for (int i = gt; i < PSTR1*256; i += NBLK*NTHR) {
            int p = i >> 8, cp = i & 255;
            int r = (176 + 2*p) - 128;   // Whh1 column for even row of this pair
            int c0 = 2*cp;
            d_Wstream2[i] = make_ulonglong2(
                pack2(__ldg(&Whh1[c0*HH + r]),     __ldg(&Whh1[c0*HH + r + 1])),
                pack2(__ldg(&Whh1[(c0+1)*HH + r]), __ldg(&Whh1[(c0+1)*HH + r + 1])));
        }
    }

    // tier 1: smem paired-weight cache
    for (int idx = tid; idx < PS*256; idx += NTHR) {
        int p = idx >> 8, cp = idx & 255;
        wsp[idx] = make_ulonglong2(
            pack2(gw(2*p, 2*cp),   gw(2*p+1, 2*cp)),
            pack2(gw(2*p, 2*cp+1), gw(2*p+1, 2*cp+1)));
    }
    // tier 2: register paired-weight cache
    ulonglong2 wreg[PR];
    #pragma unroll
    for (int r = 0; r < PR; ++r) {
        int k = 2*(PS + r);
        wreg[r] = make_ulonglong2(
            pack2(gw(k, 2*tid),   gw(k+1, 2*tid)),
            pack2(gw(k, 2*tid+1), gw(k+1, 2*tid+1)));
    }

    // zero all h-pairs (covers recurrent region AND zero-pad rows)
    for (int i = tid; i < P*4; i += NTHR) hp[i] = 0ull;

    const float bc0 = __ldg(&bih[2*tid])   + __ldg(&bhh[2*tid]);
    const float bc1 = __ldg(&bih[2*tid+1]) + __ldg(&bhh[2*tid+1]);

    float cst[2] = {0.f, 0.f};
    const int dj  = tid & (HH-1);        // h index for phase D
    const int db  = (tid >> 7) * 2;      // first of 2 batches for phase D

    // ---- xin prefetch state ----
    // L1: thread -> (b = tid>>6, pair = tid&63), float2 per step (covers 64 pairs x 4 b)
    // L0: threads <52 -> (b = tid/13, k = tid%13), scalar per step
    const int pfb = (LAYER == 0) ? ((tid < BC*NI) ? tid/NI : 0) : (tid >> 6);
    const int pfk = (LAYER == 0) ? ((tid < BC*NI) ? tid - pfb*NI : 0) : (tid & 63);
    const float* xpf = (LAYER == 0)
        ? xin + ((size_t)(b0 + pfb)*TT)*IN + pfk
        : xin + ((size_t)(b0 + pfb)*TT)*HH + 2*pfk;
    float pf0 = 0.f, pf1 = 0.f;
    if (LAYER == 0) { if (tid < BC*NI) pf0 = __ldg(xpf); }
    else            { float2 v = __ldg((const float2*)xpf); pf0 = v.x; pf1 = v.y; }

    __syncthreads();

    const ulonglong2* hpq = (const ulonglong2*)hp;

    for (int t = 0; t < TT; ++t) {
        // ---- phase A: publish this step's input slice (k-paired) ----
        if (LAYER == 0) {
            if (tid < BC*NI) hpf[((pfk >> 1)*4 + pfb)*2 + (pfk & 1)] = pf0;
        } else {
            hp[pfk*4 + pfb] = pack2(pf0, pf1);
        }
        __syncthreads();   // covers phase-A writes AND prev-step recurrent-h writes

        // prefetch next step's input (latency hidden behind phase B)
        if (t + 1 < TT) {
            const float* p = xpf + (size_t)(t+1)*IN;
            if (LAYER == 0) { if (tid < BC*NI) pf0 = __ldg(p); }
            else            { float2 v = __ldg((const float2*)p); pf0 = v.x; pf1 = v.y; }
        }

        // ---- phase B: gate pre-activations; acc lanes = (even-k sum, odd-k sum) ----
        ull A00 = pack2(bc0, 0.f), A01 = A00, A02 = A00, A03 = A00;  // col c0, b0..3
        ull A10 = pack2(bc1, 0.f), A11 = A10, A12 = A10, A13 = A10;  // col c1, b0..3

        auto rowfma = [&](ulonglong2 w, int p){
            ulonglong2 hA = hpq[p*2];      // (h-pair b0, h-pair b1)
            ulonglong2 hB = hpq[p*2 + 1];  // (h-pair b2, h-pair b3)
            A00 = ffma2(hA.x, w.x, A00);  A01 = ffma2(hA.y, w.x, A01);
            A02 = ffma2(hB.x, w.x, A02);  A03 = ffma2(hB.y, w.x, A03);
            A10 = ffma2(hA.x, w.y, A10);  A11 = ffma2(hA.y, w.y, A11);
            A12 = ffma2(hB.x, w.y, A12);  A13 = ffma2(hB.y, w.y, A13);
        };

        if (PSTR > 0) {
            ulonglong2 buf[4][CH];
            auto ldch = [&](int slot, int c){
                #pragma unroll
                for (int i = 0; i < CH; ++i)
                    buf[slot][i] = __ldg(&d_Wstream2[(c*CH + i)*256 + tid]);
            };
            ldch(0, 0); ldch(1, 1); ldch(2, 2);      // 3-chunk lookahead,
            #pragma unroll
            for (int r = 0; r < PR; ++r) rowfma(wreg[r], PS + r);  // hidden by reg tier

            // 20 chunk iters; smem interleave 12x3 + 8x2 = 52 pairs
            #pragma unroll
            for (int c = 0; c < NCH; ++c) {
                if (c + 3 < NCH) ldch((c+3) & 3, c+3);
                #pragma unroll
                for (int i = 0; i < CH; ++i) rowfma(buf[c & 3][i], PS + PR + c*CH + i);
                const int k0 = (c < 12) ? 3*c : 36 + 2*(c-12);
                const int n  = (c < 12) ? 3 : 2;
                #pragma unroll
                for (int k = 0; k < n; ++k) rowfma(wsp[(k0+k)*256 + tid], k0 + k);
            }
        } else {
            #pragma unroll
            for (int r = 0; r < PR; ++r) rowfma(wreg[r], PS + r);
            #pragma unroll 4
            for (int p = 0; p < PS; ++p) rowfma(wsp[p*256 + tid], p);
        }

        // ---- phase C: horizontal add + publish ----
        gs2[0*256 + tid] = pack2(sum2(A00), sum2(A10));
        gs2[1*256 + tid] = pack2(sum2(A01), sum2(A11));
        gs2[2*256 + tid] = pack2(sum2(A02), sum2(A12));
        gs2[3*256 + tid] = pack2(sum2(A03), sum2(A13));
        __syncthreads();

        // ---- phase D: gates + state update (thread -> (dj, 2 batches)) ----
        #pragma unroll
        for (int q = 0; q < 2; ++q) {
            int b = db + q;
            float gi = gsf[b*GG +          dj];
            float gf = gsf[b*GG +   HH  +  dj];
            float gg = gsf[b*GG + 2*HH  +  dj];
            float go = gsf[b*GG + 3*HH  +  dj];
            float ig = sigf(gi);                           // accurate: feeds c integral
            float fg = sigf(gf);                           // accurate
            float gv = tanh_(gg);                          // accurate
            float og = fmaf(tanhap(0.5f*go), 0.5f, 0.5f);  // approx: output path
            float c  = fg*cst[q] + ig*gv;
            cst[q] = c;
            float h = og * tanhap(c);                      // approx: output path
            int R = IN + dj;
            hpf[((R >> 1)*4 + b)*2 + (R & 1)] = h;
            if (LAYER == 0) {
                d_h1[((size_t)(b0 + b)*TT + t)*HH + dj] = h;
            }
        }
        // next iteration's phase-A sync orders D's hp writes before the k-loop
    }

    // ---- fused FC epilogue (layer 1 only): out[b][c] = h . Wfc[c] + bfc[c] ----
    if (LAYER == 1) {
        __syncthreads();                   // all final h visible in hp
        int g = tid >> 4;                  // 16 groups of 16 threads
        int l = tid & 15;
        int b = g >> 2, c = g & 3;
        float s = 0.f;
        #pragma unroll
        for (int q = 0; q < 8; ++q) {
            int j = l + 16*q;
            int R = HH + j;
            float hv = hpf[((R >> 1)*4 + b)*2 + (R & 1)];
            s += hv * __ldg(&Wfc[c*HH + j]);
        }
        #pragma unroll
        for (int o = 8; o; o >>= 1) s += __shfl_xor_sync(0xffffffffu, s, o, 16);
        if (l == 0) out[(b0 + b)*4 + c] = s + __ldg(&bfc[c]);
    }
}

// -------- launch --------
extern "C" void kernel_launch(void* const* d_in, const int* in_sizes, int n_in,
                              void* d_out, int out_size)
{
    const float* x    = (const float*)d_in[0];
    const float* Wih0 = (const float*)d_in[1];
    const float* Whh0 = (const float*)d_in[2];
    const float* bih0 = (const float*)d_in[3];
    const float* bhh0 = (const float*)d_in[4];
    const float* Wih1 = (const float*)d_in[5];
    const float* Whh1 = (const float*)d_in[6];
    const float* bih1 = (const float*)d_in[7];
    const float* bhh1 = (const float*)d_in[8];
    const float* Wfc  = (const float*)d_in[9];
    const float* bfc  = (const float*)d_in[10];
    float* out = (float*)d_out;

    // smem bytes: wsp PS*256*16 + hp P*4*8 + gs2 4*256*8
    constexpr int SMEM0 = PS*256*16 + 72*4*8  + 4*256*8;   // 223,488 B
    constexpr int SMEM1 = PS*256*16 + 128*4*8 + 4*256*8;   // 225,280 B

    cudaFuncSetAttribute(lstm_layer<0>, cudaFuncAttributeMaxDynamicSharedMemorySize, SMEM0);
    cudaFuncSetAttribute(lstm_layer<1>, cudaFuncAttributeMaxDynamicSharedMemorySize, SMEM1);

    lstm_layer<0><<<NBLK, NTHR, SMEM0>>>(x, Wih0, Whh0, bih0, bhh0, Whh1,
                                         nullptr, nullptr, nullptr);
    lstm_layer<1><<<NBLK, NTHR, SMEM1>>>(nullptr, Wih1, Whh1, bih1, bhh1, nullptr,
                                         Wfc, bfc, out);
}